// round 12
// baseline (speedup 1.0000x reference)
#include <cuda_runtime.h>
#include <cuda_bf16.h>
#include <cstdint>

#define BB 512
#define SS 200
#define HH 256
#define MROWS (BB * SS)        // 102400 = 1600 * 64
#define MT64 1600
#define NCH 8                  // K chunks of 32
#define CHUNK_BYTES 16384      // conv chunk: hi 8KB | lo 8KB (tiled128)

// ---------------- scratch (no cudaMalloc allowed) ----------------
__device__ float g_l[BB * HH];
__device__ float g_sc[2 * MROWS];  // partial scores per n-half
__device__ __align__(128) char g_Xc[(size_t)(MT64 / 2) * NCH * CHUNK_BYTES];  // 100MB
__device__ __align__(128) char g_Uc[2 * NCH * CHUNK_BYTES];                   // 256KB

// ---------------- helpers ----------------
__device__ __forceinline__ uint32_t smem_u32(const void* p) {
    uint32_t a;
    asm("{ .reg .u64 t; cvta.to.shared.u64 t, %1; cvt.u32.u64 %0, t; }" : "=r"(a) : "l"(p));
    return a;
}
__device__ __forceinline__ uint32_t pack_bf2(float x, float y) {
    uint32_t a = (uint32_t)__bfloat16_as_ushort(__float2bfloat16_rn(x));
    uint32_t b = (uint32_t)__bfloat16_as_ushort(__float2bfloat16_rn(y));
    return a | (b << 16);
}

// MUFU-free tanh (FMA/ALU pipes only); |err| <= ~3.4e-5
__device__ __forceinline__ float tanh_fma(float x) {
    float t = fminf(fabsf(x), 5.5f) * 2.8853900817779268f;  // 2*log2(e)*|x|
    int n = __float2int_rn(t);
    float f = t - (float)n;
    float p = 1.5403530393381608e-4f;
    p = fmaf(p, f, 1.3333558146428443e-3f);
    p = fmaf(p, f, 9.6181291076284772e-3f);
    p = fmaf(p, f, 5.5504108664821580e-2f);
    p = fmaf(p, f, 2.4022650695910071e-1f);
    p = fmaf(p, f, 6.9314718055994531e-1f);
    p = fmaf(p, f, 1.0f);
    float E = __int_as_float(__float_as_int(p) + (n << 23)); // e^{2|x|}
    float D = E + 1.0f;
    float r = __int_as_float(0x7EF311C3 - __float_as_int(D));
    r = r * fmaf(-D, r, 2.0f);
    r = r * fmaf(-D, r, 2.0f);
    r = r * fmaf(-D, r, 2.0f);
    float y = fmaf(-2.0f, r, 1.0f);
    return copysignf(y, x);
}

__device__ __forceinline__ void ldsm4(uint32_t* r, uint32_t addr) {
    asm volatile("ldmatrix.sync.aligned.m8n8.x4.shared.b16 {%0,%1,%2,%3}, [%4];"
                 : "=r"(r[0]), "=r"(r[1]), "=r"(r[2]), "=r"(r[3]) : "r"(addr));
}
__device__ __forceinline__ void mma_bf16(float* c, const uint32_t* a, uint32_t b0, uint32_t b1) {
    asm volatile(
        "mma.sync.aligned.m16n8k16.row.col.f32.bf16.bf16.f32 "
        "{%0,%1,%2,%3}, {%4,%5,%6,%7}, {%8,%9}, {%0,%1,%2,%3};"
        : "+f"(c[0]), "+f"(c[1]), "+f"(c[2]), "+f"(c[3])
        : "r"(a[0]), "r"(a[1]), "r"(a[2]), "r"(a[3]), "r"(b0), "r"(b1));
}
#define CPA16(dst, src) \
    asm volatile("cp.async.cg.shared.global [%0], [%1], 16;" :: "r"(dst), "l"(src))

// ---------------------------------------------------------------------------
// conv: fp32 rows -> tiled128 bf16 hi/lo chunks (R9/R10-proven).
// Chunk = 128 rows x 32 k. Tile (rg, kg) = 8 rows x 8 k, 128B at (rg*4+kg)*128.
// Layout: [mt128][kc][hi 8KB | lo 8KB]. blockIdx = mt*8 + kc, thread = row.
// ---------------------------------------------------------------------------
__global__ void __launch_bounds__(128) conv_kernel(const float* __restrict__ S,
                                                   char* __restrict__ D) {
    const int blk = blockIdx.x;
    const int mt = blk >> 3;
    const int kc = blk & 7;
    const int r = threadIdx.x;

    const float* src = S + (size_t)(mt * 128 + r) * HH + kc * 32;
    char* dst = D + (size_t)blk * CHUNK_BYTES;
    const uint32_t rowbase = (uint32_t)((r >> 3) * 4 * 128 + (r & 7) * 16);

#pragma unroll
    for (int q = 0; q < 8; q++) {
        float4 v = *(const float4*)(src + q * 4);
        float4 h;
        h.x = __bfloat162float(__float2bfloat16_rn(v.x));
        h.y = __bfloat162float(__float2bfloat16_rn(v.y));
        h.z = __bfloat162float(__float2bfloat16_rn(v.z));
        h.w = __bfloat162float(__float2bfloat16_rn(v.w));
        uint2 ph, pl;
        ph.x = pack_bf2(v.x, v.y);
        ph.y = pack_bf2(v.z, v.w);
        pl.x = pack_bf2(v.x - h.x, v.y - h.y);
        pl.y = pack_bf2(v.z - h.z, v.w - h.w);
        uint32_t off = rowbase + (uint32_t)((q >> 1) * 128 + (q & 1) * 8);
        *(uint2*)(dst + off) = ph;
        *(uint2*)(dst + 8192 + off) = pl;
    }
}

// ---------------------------------------------------------------------------
// l[b,k] = sum_h W[k,h] * last_memory[b,h]
// ---------------------------------------------------------------------------
__global__ void __launch_bounds__(256) l_kernel(const float* __restrict__ lastm,
                                                const float* __restrict__ W) {
    __shared__ float lm[HH];
    __shared__ float Wt[32][HH + 1];
    const int b = blockIdx.x;
    const int tid = threadIdx.x;

    lm[tid] = lastm[b * HH + tid];
    __syncthreads();

    float acc = 0.0f;
    for (int h0 = 0; h0 < HH; h0 += 32) {
#pragma unroll
        for (int q = 0; q < 8; q++) {
            int f = tid + 256 * q;
            int k = f >> 3;
            int hq = f & 7;
            float4 v = *(const float4*)(W + k * HH + h0 + hq * 4);
            Wt[hq * 4 + 0][k] = v.x;
            Wt[hq * 4 + 1][k] = v.y;
            Wt[hq * 4 + 2][k] = v.z;
            Wt[hq * 4 + 3][k] = v.w;
        }
        __syncthreads();
#pragma unroll
        for (int hh = 0; hh < 32; hh++)
            acc = fmaf(Wt[hh][tid], lm[h0 + hh], acc);
        __syncthreads();
    }
    g_l[b * HH + tid] = acc;
}

// ---------------------------------------------------------------------------
// GEMM: CTA = 64 rows x 128 cols (nh half), 256 thr = 8 warps (2m x 4n),
// warp tile 32x32, 3 CTAs/SM (24 warps, 6/SMSP). bf16 split-3 mma.sync,
// term-major ordering (RAW reuse distance 8), WARP-STAGGERED k0 phases
// (odd warps do k0=1 first) to interleave LDSM/MMA bursts across warps.
// 3-stage cp.async ring over 8 K-chunks of 32, 1 sync per chunk.
// Stage = [Ahi 4KB | Alo 4KB | Bhi 8KB | Blo 8KB] = 24KB.
// ---------------------------------------------------------------------------
constexpr uint32_t STG = 24576;
constexpr uint32_t GEMM_SMEM = 3 * STG;  // 72KB -> 3 CTAs/SM

__global__ void __launch_bounds__(256, 3) gemm_kernel(const float* __restrict__ Vv) {
    extern __shared__ __align__(1024) char smem[];
    __shared__ float vsm[128];
    __shared__ float s_red[4][64];

    const uint32_t sb = smem_u32(smem);
    const int tid = threadIdx.x;
    const int lane = tid & 31;
    const int wid = tid >> 5;
    const int wm = wid & 1;       // 2 m-warps x 32 rows
    const int wn = wid >> 1;      // 4 n-warps x 32 cols
    const int m = blockIdx.x;     // 64-row tile
    const int nh = blockIdx.y;
    const int kstag = wid & 1;    // k0 phase stagger

    if (tid < 128) vsm[tid] = Vv[nh * 128 + tid];

    float acc[2][4][4];
#pragma unroll
    for (int i = 0; i < 2; i++)
#pragma unroll
        for (int j = 0; j < 4; j++)
#pragma unroll
            for (int k = 0; k < 4; k++) acc[i][j][k] = 0.0f;

    // stage loader: A = half of a conv 128-tile (4KB hi + 4KB lo), B = 16KB
    auto stage = [&](int kc, uint32_t sbase) {
        const char* xb = g_Xc + ((size_t)(m >> 1) * NCH + kc) * CHUNK_BYTES
                       + (m & 1) * 4096;
        const char* us = g_Uc + ((size_t)nh * NCH + kc) * CHUNK_BYTES;
        uint32_t o1 = (uint32_t)tid * 16u;           // 4KB / 256 thr
        CPA16(sbase + o1,         xb + o1);          // A hi
        CPA16(sbase + 4096u + o1, xb + 8192 + o1);   // A lo
        uint32_t o2 = (uint32_t)tid * 64u;           // 16KB / 256 thr
        uint32_t d2 = sbase + 8192u + o2;
        CPA16(d2 + 0u,  us + o2);      CPA16(d2 + 16u, us + o2 + 16);
        CPA16(d2 + 32u, us + o2 + 32); CPA16(d2 + 48u, us + o2 + 48);
        asm volatile("cp.async.commit_group;");
    };
    stage(0, sb);
    stage(1, sb + STG);

    // ldmatrix lane addressing (tiled128)
    const uint32_t lb = (uint32_t)((lane & 7) * 16);
    const uint32_t ab1 = (uint32_t)((lane >> 3) & 1);
    const uint32_t ab2 = (uint32_t)(lane >> 4);

    for (int kc = 0; kc < NCH; kc++) {
        if (kc < NCH - 1) asm volatile("cp.async.wait_group 1;");
        else              asm volatile("cp.async.wait_group 0;");
        __syncthreads();
        if (kc + 2 < NCH) stage(kc + 2, sb + (uint32_t)((kc + 2) % 3) * STG);

        const uint32_t cur = sb + (uint32_t)(kc % 3) * STG;

#pragma unroll
        for (int k0i = 0; k0i < 2; k0i++) {
            const int k0 = k0i ^ kstag;              // staggered phase per warp
            const uint32_t kg = (uint32_t)(k0 * 2);

            uint32_t Ahi[2][4], Alo[2][4];
#pragma unroll
            for (int mt = 0; mt < 2; mt++) {
                uint32_t tix = ((uint32_t)(wm * 4 + mt * 2) + ab1) * 4 + kg + ab2;
                uint32_t addr = cur + tix * 128u + lb;
                ldsm4(Ahi[mt], addr);
                ldsm4(Alo[mt], addr + 4096u);
            }
            uint32_t Bhi[2][4], Blo[2][4];
#pragma unroll
            for (int ntp = 0; ntp < 2; ntp++) {
                uint32_t tix = ((uint32_t)(wn * 4 + ntp * 2) + ab2) * 4 + kg + ab1;
                uint32_t addr = cur + 8192u + tix * 128u + lb;
                ldsm4(Bhi[ntp], addr);
                ldsm4(Blo[ntp], addr + 8192u);
            }

            // term-major: 8 independent MMAs per term (reuse distance 8)
#pragma unroll
            for (int mt = 0; mt < 2; mt++)
#pragma unroll
                for (int ntp = 0; ntp < 2; ntp++)
#pragma unroll
                    for (int sub = 0; sub < 2; sub++)
                        mma_bf16(acc[mt][ntp * 2 + sub], Ahi[mt],
                                 Bhi[ntp][sub * 2], Bhi[ntp][sub * 2 + 1]);
#pragma unroll
            for (int mt = 0; mt < 2; mt++)
#pragma unroll
                for (int ntp = 0; ntp < 2; ntp++)
#pragma unroll
                    for (int sub = 0; sub < 2; sub++)
                        mma_bf16(acc[mt][ntp * 2 + sub], Ahi[mt],
                                 Blo[ntp][sub * 2], Blo[ntp][sub * 2 + 1]);
#pragma unroll
            for (int mt = 0; mt < 2; mt++)
#pragma unroll
                for (int ntp = 0; ntp < 2; ntp++)
#pragma unroll
                    for (int sub = 0; sub < 2; sub++)
                        mma_bf16(acc[mt][ntp * 2 + sub], Alo[mt],
                                 Bhi[ntp][sub * 2], Bhi[ntp][sub * 2 + 1]);
        }
    }

    // Epilogue: per row, sum over this warp's 32 cols of V[n]*tanh(acc+l)
#pragma unroll
    for (int mt = 0; mt < 2; mt++) {
#pragma unroll
        for (int rh = 0; rh < 2; rh++) {
            int rowl = wm * 32 + mt * 16 + rh * 8 + (lane >> 2);
            int rowg = m * 64 + rowl;
            const float* lr = g_l + (rowg / SS) * HH + nh * 128;
            float s = 0.0f;
#pragma unroll
            for (int nt = 0; nt < 4; nt++) {
#pragma unroll
                for (int cl = 0; cl < 2; cl++) {
                    int col = wn * 32 + nt * 8 + (lane & 3) * 2 + cl;
                    float v = acc[mt][nt][rh * 2 + cl] + __ldg(lr + col);
                    s = fmaf(vsm[col], tanh_fma(v), s);
                }
            }
            s += __shfl_xor_sync(0xffffffffu, s, 1);
            s += __shfl_xor_sync(0xffffffffu, s, 2);
            if ((lane & 3) == 0) s_red[wn][rowl] = s;
        }
    }
    __syncthreads();
    if (tid < 64)
        g_sc[nh * MROWS + m * 64 + tid] =
            (s_red[0][tid] + s_red[1][tid]) + (s_red[2][tid] + s_red[3][tid]);
}

// ---------------------------------------------------------------------------
// softmax over S + float4 pooling + final projection
// ---------------------------------------------------------------------------
__global__ void __launch_bounds__(256) pool_kernel(const float* __restrict__ X,
                                                   const float* __restrict__ MW,
                                                   const float* __restrict__ Mb,
                                                   float* __restrict__ out) {
    __shared__ float sal[SS];
    __shared__ float red[8];
    __shared__ float4 red4[8];
    __shared__ float4 s_p4[4][64];
    __shared__ float pooled[HH];

    const int b = blockIdx.x;
    const int tid = threadIdx.x;
    const int lane = tid & 31;
    const int w = tid >> 5;

    float v;
    if (tid < SS) {
        int idx = b * SS + tid;
        v = g_sc[idx] + g_sc[MROWS + idx];
    } else {
        v = __int_as_float(0xff800000);
    }
    float mx = v;
#pragma unroll
    for (int o = 16; o; o >>= 1) mx = fmaxf(mx, __shfl_xor_sync(0xffffffffu, mx, o));
    if (lane == 0) red[w] = mx;
    __syncthreads();
    float bm = red[0];
#pragma unroll
    for (int i = 1; i < 8; i++) bm = fmaxf(bm, red[i]);

    float e = (tid < SS) ? __expf(v - bm) : 0.0f;
    float s = e;
#pragma unroll
    for (int o = 16; o; o >>= 1) s += __shfl_xor_sync(0xffffffffu, s, o);
    __syncthreads();
    if (lane == 0) red[w] = s;
    __syncthreads();
    float bs = 0.0f;
#pragma unroll
    for (int i = 0; i < 8; i++) bs += red[i];

    if (tid < SS) sal[tid] = e / bs;
    __syncthreads();

    // float4 pooling: 64 h-columns (float4) x 4 s-row-groups
    {
        const int g = tid >> 6;     // row-group 0..3
        const int c = tid & 63;     // float4 column
        const float4* X4 = (const float4*)(X + (size_t)b * SS * HH) + c;
        float4 a = make_float4(0.f, 0.f, 0.f, 0.f);
#pragma unroll 5
        for (int sdx = g; sdx < SS; sdx += 4) {
            float4 xv = X4[(size_t)sdx * 64];
            float al = sal[sdx];
            a.x = fmaf(al, xv.x, a.x);
            a.y = fmaf(al, xv.y, a.y);
            a.z = fmaf(al, xv.z, a.z);
            a.w = fmaf(al, xv.w, a.w);
        }
        s_p4[g][c] = a;
    }
    __syncthreads();
    if (tid < 64) {
        float4 a0 = s_p4[0][tid], a1 = s_p4[1][tid];
        float4 a2 = s_p4[2][tid], a3 = s_p4[3][tid];
        float4 t;
        t.x = (a0.x + a1.x) + (a2.x + a3.x);
        t.y = (a0.y + a1.y) + (a2.y + a3.y);
        t.z = (a0.z + a1.z) + (a2.z + a3.z);
        t.w = (a0.w + a1.w) + (a2.w + a3.w);
        *(float4*)&pooled[tid * 4] = t;
    }
    __syncthreads();

    // projection: thread = h
    float acc = pooled[tid];
    float4 p;
    p.x = acc * MW[0 * HH + tid];
    p.y = acc * MW[1 * HH + tid];
    p.z = acc * MW[2 * HH + tid];
    p.w = acc * MW[3 * HH + tid];
#pragma unroll
    for (int o = 16; o; o >>= 1) {
        p.x += __shfl_xor_sync(0xffffffffu, p.x, o);
        p.y += __shfl_xor_sync(0xffffffffu, p.y, o);
        p.z += __shfl_xor_sync(0xffffffffu, p.z, o);
        p.w += __shfl_xor_sync(0xffffffffu, p.w, o);
    }
    if (lane == 0) red4[w] = p;
    __syncthreads();
    if (tid == 0) {
        float4 t = red4[0];
#pragma unroll
        for (int i = 1; i < 8; i++) {
            t.x += red4[i].x; t.y += red4[i].y; t.z += red4[i].z; t.w += red4[i].w;
        }
        out[b * 4 + 0] = t.x + Mb[0];
        out[b * 4 + 1] = t.y + Mb[1];
        out[b * 4 + 2] = t.z + Mb[2];
        out[b * 4 + 3] = t.w + Mb[3];
    }
}

// ---------------------------------------------------------------------------
extern "C" void kernel_launch(void* const* d_in, const int* in_sizes, int n_in,
                              void* d_out, int out_size) {
    const float* X     = (const float*)d_in[0];
    const float* lastm = (const float*)d_in[1];
    const float* U     = (const float*)d_in[2];
    const float* W     = (const float*)d_in[3];
    const float* Vv    = (const float*)d_in[4];
    const float* MW    = (const float*)d_in[5];
    const float* Mb    = (const float*)d_in[6];
    float* out = (float*)d_out;

    char *xc, *uc;
    cudaGetSymbolAddress((void**)&xc, g_Xc);
    cudaGetSymbolAddress((void**)&uc, g_Uc);

    cudaFuncSetAttribute(gemm_kernel, cudaFuncAttributeMaxDynamicSharedMemorySize, GEMM_SMEM);

    conv_kernel<<<2 * NCH, 128>>>(U, uc);               // U -> tiled128
    conv_kernel<<<(MT64 / 2) * NCH, 128>>>(X, xc);      // X -> tiled128
    l_kernel<<<BB, 256>>>(lastm, W);
    gemm_kernel<<<dim3(MT64, 2), 256, GEMM_SMEM>>>(Vv);
    pool_kernel<<<BB, 256>>>(X, MW, Mb, out);
}

// round 13
// speedup vs baseline: 1.0533x; 1.0533x over previous
#include <cuda_runtime.h>
#include <cuda_bf16.h>
#include <cstdint>

#define BB 512
#define SS 200
#define HH 256
#define MROWS (BB * SS)        // 102400 = 1600 * 64
#define MT64 1600
#define NCH 8                  // K chunks of 32
#define CHUNK_BYTES 16384      // conv-U chunk: hi 8KB | lo 8KB (tiled128)

// ---------------- scratch (no cudaMalloc allowed) ----------------
__device__ float g_l[BB * HH];
__device__ float g_sc[2 * MROWS];            // partial scores per n-half
__device__ __align__(128) char g_Uc[2 * NCH * CHUNK_BYTES];   // 256KB

// ---------------- helpers ----------------
__device__ __forceinline__ uint32_t smem_u32(const void* p) {
    uint32_t a;
    asm("{ .reg .u64 t; cvta.to.shared.u64 t, %1; cvt.u32.u64 %0, t; }" : "=r"(a) : "l"(p));
    return a;
}
__device__ __forceinline__ uint32_t pack_bf2(float x, float y) {
    uint32_t a = (uint32_t)__bfloat16_as_ushort(__float2bfloat16_rn(x));
    uint32_t b = (uint32_t)__bfloat16_as_ushort(__float2bfloat16_rn(y));
    return a | (b << 16);
}

// in-register split of a float2 into bf16 hi pair + bf16 lo pair
__device__ __forceinline__ void cvt_hilo(float x, float y, uint32_t& hi, uint32_t& lo) {
    hi = pack_bf2(x, y);
    float h0 = __int_as_float(hi << 16);
    float h1 = __int_as_float(hi & 0xffff0000u);
    lo = pack_bf2(x - h0, y - h1);
}

// MUFU-free tanh (FMA/ALU pipes only); |err| <= ~3.4e-5
__device__ __forceinline__ float tanh_fma(float x) {
    float t = fminf(fabsf(x), 5.5f) * 2.8853900817779268f;  // 2*log2(e)*|x|
    int n = __float2int_rn(t);
    float f = t - (float)n;
    float p = 1.5403530393381608e-4f;
    p = fmaf(p, f, 1.3333558146428443e-3f);
    p = fmaf(p, f, 9.6181291076284772e-3f);
    p = fmaf(p, f, 5.5504108664821580e-2f);
    p = fmaf(p, f, 2.4022650695910071e-1f);
    p = fmaf(p, f, 6.9314718055994531e-1f);
    p = fmaf(p, f, 1.0f);
    float E = __int_as_float(__float_as_int(p) + (n << 23)); // e^{2|x|}
    float D = E + 1.0f;
    float r = __int_as_float(0x7EF311C3 - __float_as_int(D));
    r = r * fmaf(-D, r, 2.0f);
    r = r * fmaf(-D, r, 2.0f);
    r = r * fmaf(-D, r, 2.0f);
    float y = fmaf(-2.0f, r, 1.0f);
    return copysignf(y, x);
}

__device__ __forceinline__ void ldsm4(uint32_t* r, uint32_t addr) {
    asm volatile("ldmatrix.sync.aligned.m8n8.x4.shared.b16 {%0,%1,%2,%3}, [%4];"
                 : "=r"(r[0]), "=r"(r[1]), "=r"(r[2]), "=r"(r[3]) : "r"(addr));
}
__device__ __forceinline__ void mma_bf16(float* c, const uint32_t* a, uint32_t b0, uint32_t b1) {
    asm volatile(
        "mma.sync.aligned.m16n8k16.row.col.f32.bf16.bf16.f32 "
        "{%0,%1,%2,%3}, {%4,%5,%6,%7}, {%8,%9}, {%0,%1,%2,%3};"
        : "+f"(c[0]), "+f"(c[1]), "+f"(c[2]), "+f"(c[3])
        : "r"(a[0]), "r"(a[1]), "r"(a[2]), "r"(a[3]), "r"(b0), "r"(b1));
}
#define CPA16(dst, src) \
    asm volatile("cp.async.cg.shared.global [%0], [%1], 16;" :: "r"(dst), "l"(src))

// ---------------------------------------------------------------------------
// conv (U only): fp32 rows -> tiled128 bf16 hi/lo chunks.
// Chunk = 128 rows x 32 k. Tile (rg, kg) = 8 rows x 8 k, 128B at (rg*4+kg)*128.
// Layout: [mt128][kc][hi 8KB | lo 8KB]. blockIdx = mt*8 + kc, thread = row.
// ---------------------------------------------------------------------------
__global__ void __launch_bounds__(128) conv_kernel(const float* __restrict__ S,
                                                   char* __restrict__ D) {
    const int blk = blockIdx.x;
    const int mt = blk >> 3;
    const int kc = blk & 7;
    const int r = threadIdx.x;

    const float* src = S + (size_t)(mt * 128 + r) * HH + kc * 32;
    char* dst = D + (size_t)blk * CHUNK_BYTES;
    const uint32_t rowbase = (uint32_t)((r >> 3) * 4 * 128 + (r & 7) * 16);

#pragma unroll
    for (int q = 0; q < 8; q++) {
        float4 v = *(const float4*)(src + q * 4);
        uint2 ph, pl;
        cvt_hilo(v.x, v.y, ph.x, pl.x);
        cvt_hilo(v.z, v.w, ph.y, pl.y);
        uint32_t off = rowbase + (uint32_t)((q >> 1) * 128 + (q & 1) * 8);
        *(uint2*)(dst + off) = ph;
        *(uint2*)(dst + 8192 + off) = pl;
    }
}

// ---------------------------------------------------------------------------
// l[b,k] = sum_h W[k,h] * last_memory[b,h]
// ---------------------------------------------------------------------------
__global__ void __launch_bounds__(256) l_kernel(const float* __restrict__ lastm,
                                                const float* __restrict__ W) {
    __shared__ float lm[HH];
    __shared__ float Wt[32][HH + 1];
    const int b = blockIdx.x;
    const int tid = threadIdx.x;

    lm[tid] = lastm[b * HH + tid];
    __syncthreads();

    float acc = 0.0f;
    for (int h0 = 0; h0 < HH; h0 += 32) {
#pragma unroll
        for (int q = 0; q < 8; q++) {
            int f = tid + 256 * q;
            int k = f >> 3;
            int hq = f & 7;
            float4 v = *(const float4*)(W + k * HH + h0 + hq * 4);
            Wt[hq * 4 + 0][k] = v.x;
            Wt[hq * 4 + 1][k] = v.y;
            Wt[hq * 4 + 2][k] = v.z;
            Wt[hq * 4 + 3][k] = v.w;
        }
        __syncthreads();
#pragma unroll
        for (int hh = 0; hh < 32; hh++)
            acc = fmaf(Wt[hh][tid], lm[h0 + hh], acc);
        __syncthreads();
    }
    g_l[b * HH + tid] = acc;
}

// ---------------------------------------------------------------------------
// GEMM: CTA = 64 rows x 128 cols (nh half), 256 thr = 8 warps (2m x 4n),
// warp tile 32x32, 3 CTAs/SM. bf16 split-3 mma.sync, term-major ordering.
// A path: X staged fp32 via cp.async, converted ONCE per chunk in smem to
// tiled128 hi/lo (kills the conv-X pass; bf16 hi+lo == fp32 bytes anyway).
// 2-stage ring. Stage = [Xf32 8KB | Ahi 4KB | Alo 4KB | Bhi 8KB | Blo 8KB].
// ---------------------------------------------------------------------------
constexpr uint32_t STG = 32768;
constexpr uint32_t GEMM_SMEM = 2 * STG;  // 64KB -> 3 CTAs/SM

__global__ void __launch_bounds__(256, 3) gemm_kernel(const float* __restrict__ X,
                                                      const float* __restrict__ Vv) {
    extern __shared__ __align__(1024) char smem[];
    __shared__ float vsm[128];
    __shared__ float s_red[4][64];

    const uint32_t sb = smem_u32(smem);
    const int tid = threadIdx.x;
    const int lane = tid & 31;
    const int wid = tid >> 5;
    const int wm = wid & 1;       // 2 m-warps x 32 rows
    const int wn = wid >> 1;      // 4 n-warps x 32 cols
    const int m = blockIdx.x;     // 64-row tile
    const int nh = blockIdx.y;

    if (tid < 128) vsm[tid] = Vv[nh * 128 + tid];

    float acc[2][4][4];
#pragma unroll
    for (int i = 0; i < 2; i++)
#pragma unroll
        for (int j = 0; j < 4; j++)
#pragma unroll
            for (int k = 0; k < 4; k++) acc[i][j][k] = 0.0f;

    // per-thread convert geometry: thread covers row = tid>>2, cols q*8..+8
    const int crow = tid >> 2;
    const int cq = tid & 3;
    const uint32_t coff = (uint32_t)(((crow >> 3) * 4 + cq) * 128 + (crow & 7) * 16);
    const uint32_t cxoff = (uint32_t)(crow * 128 + cq * 32);

    // stage loader: X fp32 8KB (rows m*64.., cols kc*32..+32) + B 16KB
    auto stage = [&](int kc, uint32_t sbase) {
        const char* xr = (const char*)(X + (size_t)m * 64 * HH + kc * 32)
                       + (size_t)crow * (HH * 4) + cq * 32;
        uint32_t d = sbase + cxoff;
        CPA16(d, xr); CPA16(d + 16u, xr + 16);
        const char* us = g_Uc + ((size_t)nh * NCH + kc) * CHUNK_BYTES;
        uint32_t o2 = (uint32_t)tid * 64u;
        uint32_t d2 = sbase + 16384u + o2;
        CPA16(d2 + 0u,  us + o2);      CPA16(d2 + 16u, us + o2 + 16);
        CPA16(d2 + 32u, us + o2 + 32); CPA16(d2 + 48u, us + o2 + 48);
        asm volatile("cp.async.commit_group;");
    };
    stage(0, sb);

    // ldmatrix lane addressing (tiled128)
    const uint32_t lb = (uint32_t)((lane & 7) * 16);
    const uint32_t ab1 = (uint32_t)((lane >> 3) & 1);
    const uint32_t ab2 = (uint32_t)(lane >> 4);

    for (int kc = 0; kc < NCH; kc++) {
        const uint32_t cur = sb + (uint32_t)(kc & 1) * STG;
        asm volatile("cp.async.wait_group 0;");
        __syncthreads();
        if (kc + 1 < NCH) stage(kc + 1, sb + (uint32_t)((kc + 1) & 1) * STG);

        // convert this chunk's X fp32 -> tiled128 bf16 hi/lo (off MMA path)
        {
            const char* xs = smem + (cur - sb);
            float4 v0 = *(const float4*)(xs + cxoff);
            float4 v1 = *(const float4*)(xs + cxoff + 16);
            uint4 hi, lo;
            cvt_hilo(v0.x, v0.y, hi.x, lo.x);
            cvt_hilo(v0.z, v0.w, hi.y, lo.y);
            cvt_hilo(v1.x, v1.y, hi.z, lo.z);
            cvt_hilo(v1.z, v1.w, hi.w, lo.w);
            char* as = smem + (cur - sb) + 8192;
            *(uint4*)(as + coff) = hi;
            *(uint4*)(as + 4096 + coff) = lo;
        }
        __syncthreads();

#pragma unroll
        for (int k0 = 0; k0 < 2; k0++) {
            const uint32_t kg = (uint32_t)(k0 * 2);

            uint32_t Ahi[2][4], Alo[2][4];
#pragma unroll
            for (int mt = 0; mt < 2; mt++) {
                uint32_t tix = ((uint32_t)(wm * 4 + mt * 2) + ab1) * 4 + kg + ab2;
                uint32_t addr = cur + 8192u + tix * 128u + lb;
                ldsm4(Ahi[mt], addr);
                ldsm4(Alo[mt], addr + 4096u);
            }
            uint32_t Bhi[2][4], Blo[2][4];
#pragma unroll
            for (int ntp = 0; ntp < 2; ntp++) {
                uint32_t tix = ((uint32_t)(wn * 4 + ntp * 2) + ab2) * 4 + kg + ab1;
                uint32_t addr = cur + 16384u + tix * 128u + lb;
                ldsm4(Bhi[ntp], addr);
                ldsm4(Blo[ntp], addr + 8192u);
            }

            // term-major: 8 independent MMAs per term (reuse distance 8)
#pragma unroll
            for (int mt = 0; mt < 2; mt++)
#pragma unroll
                for (int ntp = 0; ntp < 2; ntp++)
#pragma unroll
                    for (int sub = 0; sub < 2; sub++)
                        mma_bf16(acc[mt][ntp * 2 + sub], Ahi[mt],
                                 Bhi[ntp][sub * 2], Bhi[ntp][sub * 2 + 1]);
#pragma unroll
            for (int mt = 0; mt < 2; mt++)
#pragma unroll
                for (int ntp = 0; ntp < 2; ntp++)
#pragma unroll
                    for (int sub = 0; sub < 2; sub++)
                        mma_bf16(acc[mt][ntp * 2 + sub], Ahi[mt],
                                 Blo[ntp][sub * 2], Blo[ntp][sub * 2 + 1]);
#pragma unroll
            for (int mt = 0; mt < 2; mt++)
#pragma unroll
                for (int ntp = 0; ntp < 2; ntp++)
#pragma unroll
                    for (int sub = 0; sub < 2; sub++)
                        mma_bf16(acc[mt][ntp * 2 + sub], Alo[mt],
                                 Bhi[ntp][sub * 2], Bhi[ntp][sub * 2 + 1]);
        }
        __syncthreads();
    }

    // Epilogue: per row, sum over this warp's 32 cols of V[n]*tanh(acc+l)
#pragma unroll
    for (int mt = 0; mt < 2; mt++) {
#pragma unroll
        for (int rh = 0; rh < 2; rh++) {
            int rowl = wm * 32 + mt * 16 + rh * 8 + (lane >> 2);
            int rowg = m * 64 + rowl;
            const float* lr = g_l + (rowg / SS) * HH + nh * 128;
            float s = 0.0f;
#pragma unroll
            for (int nt = 0; nt < 4; nt++) {
#pragma unroll
                for (int cl = 0; cl < 2; cl++) {
                    int col = wn * 32 + nt * 8 + (lane & 3) * 2 + cl;
                    float v = acc[mt][nt][rh * 2 + cl] + __ldg(lr + col);
                    s = fmaf(vsm[col], tanh_fma(v), s);
                }
            }
            s += __shfl_xor_sync(0xffffffffu, s, 1);
            s += __shfl_xor_sync(0xffffffffu, s, 2);
            if ((lane & 3) == 0) s_red[wn][rowl] = s;
        }
    }
    __syncthreads();
    if (tid < 64)
        g_sc[nh * MROWS + m * 64 + tid] =
            (s_red[0][tid] + s_red[1][tid]) + (s_red[2][tid] + s_red[3][tid]);
}

// ---------------------------------------------------------------------------
// softmax over S + pooled + final projection (R10-proven)
// ---------------------------------------------------------------------------
__global__ void __launch_bounds__(256) pool_kernel(const float* __restrict__ X,
                                                   const float* __restrict__ MW,
                                                   const float* __restrict__ Mb,
                                                   float* __restrict__ out) {
    __shared__ float sal[SS];
    __shared__ float red[8];
    __shared__ float4 red4[8];

    const int b = blockIdx.x;
    const int tid = threadIdx.x;
    const int lane = tid & 31;
    const int w = tid >> 5;

    float v;
    if (tid < SS) {
        int idx = b * SS + tid;
        v = g_sc[idx] + g_sc[MROWS + idx];
    } else {
        v = __int_as_float(0xff800000);
    }
    float mx = v;
#pragma unroll
    for (int o = 16; o; o >>= 1) mx = fmaxf(mx, __shfl_xor_sync(0xffffffffu, mx, o));
    if (lane == 0) red[w] = mx;
    __syncthreads();
    float bm = red[0];
#pragma unroll
    for (int i = 1; i < 8; i++) bm = fmaxf(bm, red[i]);

    float e = (tid < SS) ? __expf(v - bm) : 0.0f;
    float s = e;
#pragma unroll
    for (int o = 16; o; o >>= 1) s += __shfl_xor_sync(0xffffffffu, s, o);
    __syncthreads();
    if (lane == 0) red[w] = s;
    __syncthreads();
    float bs = 0.0f;
#pragma unroll
    for (int i = 0; i < 8; i++) bs += red[i];

    if (tid < SS) sal[tid] = e / bs;
    __syncthreads();

    const float* Xb = X + (size_t)b * SS * HH + tid;
    float acc = 0.0f;
#pragma unroll 8
    for (int sdx = 0; sdx < SS; sdx++)
        acc = fmaf(sal[sdx], Xb[(size_t)sdx * HH], acc);

    float4 p;
    p.x = acc * MW[0 * HH + tid];
    p.y = acc * MW[1 * HH + tid];
    p.z = acc * MW[2 * HH + tid];
    p.w = acc * MW[3 * HH + tid];
#pragma unroll
    for (int o = 16; o; o >>= 1) {
        p.x += __shfl_xor_sync(0xffffffffu, p.x, o);
        p.y += __shfl_xor_sync(0xffffffffu, p.y, o);
        p.z += __shfl_xor_sync(0xffffffffu, p.z, o);
        p.w += __shfl_xor_sync(0xffffffffu, p.w, o);
    }
    if (lane == 0) red4[w] = p;
    __syncthreads();
    if (tid == 0) {
        float4 t = red4[0];
#pragma unroll
        for (int i = 1; i < 8; i++) {
            t.x += red4[i].x; t.y += red4[i].y; t.z += red4[i].z; t.w += red4[i].w;
        }
        out[b * 4 + 0] = t.x + Mb[0];
        out[b * 4 + 1] = t.y + Mb[1];
        out[b * 4 + 2] = t.z + Mb[2];
        out[b * 4 + 3] = t.w + Mb[3];
    }
}

// ---------------------------------------------------------------------------
extern "C" void kernel_launch(void* const* d_in, const int* in_sizes, int n_in,
                              void* d_out, int out_size) {
    const float* X     = (const float*)d_in[0];
    const float* lastm = (const float*)d_in[1];
    const float* U     = (const float*)d_in[2];
    const float* W     = (const float*)d_in[3];
    const float* Vv    = (const float*)d_in[4];
    const float* MW    = (const float*)d_in[5];
    const float* Mb    = (const float*)d_in[6];
    float* out = (float*)d_out;

    char* uc;
    cudaGetSymbolAddress((void**)&uc, g_Uc);

    cudaFuncSetAttribute(gemm_kernel, cudaFuncAttributeMaxDynamicSharedMemorySize, GEMM_SMEM);

    conv_kernel<<<2 * NCH, 128>>>(U, uc);               // U -> tiled128
    l_kernel<<<BB, 256>>>(lastm, W);
    gemm_kernel<<<dim3(MT64, 2), 256, GEMM_SMEM>>>(X, Vv);
    pool_kernel<<<BB, 256>>>(X, MW, Mb, out);
}

// round 15
// speedup vs baseline: 1.2389x; 1.1762x over previous
#include <cuda_runtime.h>
#include <cuda_bf16.h>
#include <cstdint>

#define BB 512
#define SS 200
#define HH 256
#define MROWS (BB * SS)        // 102400 = 1600 * 64
#define MT64 1600
#define NCH 16                 // K chunks of 16
#define UCHUNK 8192            // U chunk: hi 4KB | lo 4KB (tiled128, 128 cols x 16 k)

// ---------------- scratch (no cudaMalloc allowed) ----------------
__device__ float g_l[BB * HH];
__device__ float g_sc[2 * MROWS];            // partial scores per n-half
__device__ __align__(128) char g_Uc[2 * NCH * UCHUNK];   // 256KB

// ---------------- helpers ----------------
__device__ __forceinline__ uint32_t smem_u32(const void* p) {
    uint32_t a;
    asm("{ .reg .u64 t; cvta.to.shared.u64 t, %1; cvt.u32.u64 %0, t; }" : "=r"(a) : "l"(p));
    return a;
}
__device__ __forceinline__ uint32_t pack_bf2(float x, float y) {
    uint32_t a = (uint32_t)__bfloat16_as_ushort(__float2bfloat16_rn(x));
    uint32_t b = (uint32_t)__bfloat16_as_ushort(__float2bfloat16_rn(y));
    return a | (b << 16);
}
__device__ __forceinline__ void cvt_hilo(float x, float y, uint32_t& hi, uint32_t& lo) {
    hi = pack_bf2(x, y);
    float h0 = __int_as_float(hi << 16);
    float h1 = __int_as_float(hi & 0xffff0000u);
    lo = pack_bf2(x - h0, y - h1);
}

// MUFU-free tanh (FMA/ALU pipes only); |err| <= ~3.4e-5
__device__ __forceinline__ float tanh_fma(float x) {
    float t = fminf(fabsf(x), 5.5f) * 2.8853900817779268f;  // 2*log2(e)*|x|
    int n = __float2int_rn(t);
    float f = t - (float)n;
    float p = 1.5403530393381608e-4f;
    p = fmaf(p, f, 1.3333558146428443e-3f);
    p = fmaf(p, f, 9.6181291076284772e-3f);
    p = fmaf(p, f, 5.5504108664821580e-2f);
    p = fmaf(p, f, 2.4022650695910071e-1f);
    p = fmaf(p, f, 6.9314718055994531e-1f);
    p = fmaf(p, f, 1.0f);
    float E = __int_as_float(__float_as_int(p) + (n << 23)); // e^{2|x|}
    float D = E + 1.0f;
    float r = __int_as_float(0x7EF311C3 - __float_as_int(D));
    r = r * fmaf(-D, r, 2.0f);
    r = r * fmaf(-D, r, 2.0f);
    r = r * fmaf(-D, r, 2.0f);
    float y = fmaf(-2.0f, r, 1.0f);
    return copysignf(y, x);
}

__device__ __forceinline__ void ldsm4(uint32_t* r, uint32_t addr) {
    asm volatile("ldmatrix.sync.aligned.m8n8.x4.shared.b16 {%0,%1,%2,%3}, [%4];"
                 : "=r"(r[0]), "=r"(r[1]), "=r"(r[2]), "=r"(r[3]) : "r"(addr));
}
__device__ __forceinline__ void mma_bf16(float* c, const uint32_t* a, uint32_t b0, uint32_t b1) {
    asm volatile(
        "mma.sync.aligned.m16n8k16.row.col.f32.bf16.bf16.f32 "
        "{%0,%1,%2,%3}, {%4,%5,%6,%7}, {%8,%9}, {%0,%1,%2,%3};"
        : "+f"(c[0]), "+f"(c[1]), "+f"(c[2]), "+f"(c[3])
        : "r"(a[0]), "r"(a[1]), "r"(a[2]), "r"(a[3]), "r"(b0), "r"(b1));
}
#define CPA16(dst, src) \
    asm volatile("cp.async.cg.shared.global [%0], [%1], 16;" :: "r"(dst), "l"(src))

// ---------------------------------------------------------------------------
// conv (U only): fp32 -> tiled128 bf16 hi/lo, chunks of k=16.
// Chunk = 128 U-rows x 16 k. Tile (colgrp, kg) = 8 rows x 8 k, 128B at
// (colgrp*2 + kg)*128. Layout: [nh][kc][hi 4KB | lo 4KB].
// blockIdx = nh*16 + kc, thread = U-row.
// ---------------------------------------------------------------------------
__global__ void __launch_bounds__(128) conv_kernel(const float* __restrict__ S,
                                                   char* __restrict__ D) {
    const int blk = blockIdx.x;
    const int kc = blk & 15;
    const int r = threadIdx.x;

    const float* src = S + (size_t)((blk >> 4) * 128 + r) * HH + kc * 16;
    char* dst = D + (size_t)blk * UCHUNK;
    const uint32_t rowbase = (uint32_t)((r >> 3) * 2 * 128 + (r & 7) * 16);

#pragma unroll
    for (int q = 0; q < 4; q++) {
        float4 v = *(const float4*)(src + q * 4);
        uint2 ph, pl;
        cvt_hilo(v.x, v.y, ph.x, pl.x);
        cvt_hilo(v.z, v.w, ph.y, pl.y);
        uint32_t off = rowbase + (uint32_t)((q >> 1) * 128 + (q & 1) * 8);
        *(uint2*)(dst + off) = ph;
        *(uint2*)(dst + 4096 + off) = pl;
    }
}

// ---------------------------------------------------------------------------
// l[b,k] = sum_h W[k,h] * last_memory[b,h]
// ---------------------------------------------------------------------------
__global__ void __launch_bounds__(256) l_kernel(const float* __restrict__ lastm,
                                                const float* __restrict__ W) {
    __shared__ float lm[HH];
    __shared__ float Wt[32][HH + 1];
    const int b = blockIdx.x;
    const int tid = threadIdx.x;

    lm[tid] = lastm[b * HH + tid];
    __syncthreads();

    float acc = 0.0f;
    for (int h0 = 0; h0 < HH; h0 += 32) {
#pragma unroll
        for (int q = 0; q < 8; q++) {
            int f = tid + 256 * q;
            int k = f >> 3;
            int hq = f & 7;
            float4 v = *(const float4*)(W + k * HH + h0 + hq * 4);
            Wt[hq * 4 + 0][k] = v.x;
            Wt[hq * 4 + 1][k] = v.y;
            Wt[hq * 4 + 2][k] = v.z;
            Wt[hq * 4 + 3][k] = v.w;
        }
        __syncthreads();
#pragma unroll
        for (int hh = 0; hh < 32; hh++)
            acc = fmaf(Wt[hh][tid], lm[h0 + hh], acc);
        __syncthreads();
    }
    g_l[b * HH + tid] = acc;
}

// ---------------------------------------------------------------------------
// GEMM (fused conv-X): CTA = 64 rows x 128 cols, 256 thr = 8 warps (2m x 4n),
// warp tile 32x32, 3 CTAs/SM. X staged fp32 via cp.async (ring x4), converted
// to tiled128 bf16 hi/lo one chunk AHEAD of its MMA use (A ring x2) -> one
// __syncthreads per chunk. B (U) via cp.async ring x4, prefetch distance 3.
// K chunks of 16. bf16 split-3 mma.sync, term-major.
// smem: [X 4x4KB @0][A 2x4KB @16K][B 4x8KB @24K] = 56KB.
// ---------------------------------------------------------------------------
constexpr uint32_t AOFF = 16384;
constexpr uint32_t BOFF = 24576;
constexpr uint32_t GEMM_SMEM = 57344;  // 56KB -> 3 CTAs/SM

__global__ void __launch_bounds__(256, 3) gemm_kernel(const float* __restrict__ X,
                                                      const float* __restrict__ Vv) {
    extern __shared__ __align__(1024) char smem[];
    __shared__ float vsm[128];
    __shared__ float s_red[4][64];

    const uint32_t sb = smem_u32(smem);
    const int tid = threadIdx.x;
    const int lane = tid & 31;
    const int wid = tid >> 5;
    const int wm = wid & 1;       // 2 m-warps x 32 rows
    const int wn = wid >> 1;      // 4 n-warps x 32 cols
    const int m = blockIdx.x;     // 64-row tile
    const int nh = blockIdx.y;

    if (tid < 128) vsm[tid] = Vv[nh * 128 + tid];

    float acc[2][4][4];
#pragma unroll
    for (int i = 0; i < 2; i++)
#pragma unroll
        for (int j = 0; j < 4; j++)
#pragma unroll
            for (int k = 0; k < 4; k++) acc[i][j][k] = 0.0f;

    // convert geometry: thread = (row = tid>>2, 4 floats at ks = (tid&3)*4)
    const int crow = tid >> 2;
    const uint32_t cxread = (uint32_t)(crow * 64 + (tid & 3) * 16);
    const uint32_t cwrit = (uint32_t)(((crow >> 3) * 2 + ((tid & 3) >> 1)) * 128
                                      + (crow & 7) * 16 + (tid & 1) * 8);
    const char* xbase = (const char*)(X + (size_t)m * 64 * HH)
                      + (size_t)crow * (HH * 4) + (tid & 3) * 16;

    // group G_j = { B(j) -> Bslot j%4 ; X(j+1) -> Xslot (j+1)%4 }
    auto stageG = [&](int j) {
        if (j < NCH) {
            const char* us = g_Uc + ((size_t)nh * NCH + j) * UCHUNK;
            uint32_t o = (uint32_t)tid * 32u;
            uint32_t d = sb + BOFF + (uint32_t)(j & 3) * 8192u + o;
            CPA16(d, us + o); CPA16(d + 16u, us + o + 16);
            int jx = j + 1;
            if (jx < NCH)
                CPA16(sb + (uint32_t)(jx & 3) * 4096u + cxread, xbase + jx * 64);
        }
        asm volatile("cp.async.commit_group;");
    };

    // prologue: P = {X(0)}, then G_0, G_1, G_2
    CPA16(sb + cxread, xbase);
    asm volatile("cp.async.commit_group;");
    stageG(0); stageG(1); stageG(2);

    asm volatile("cp.async.wait_group 3;");   // P done
    __syncthreads();
    {   // convert X(0) -> A slot 0
        float4 v = *(const float4*)(smem + cxread);
        uint2 hi, lo;
        cvt_hilo(v.x, v.y, hi.x, lo.x);
        cvt_hilo(v.z, v.w, hi.y, lo.y);
        char* as = smem + AOFF + cwrit;
        *(uint2*)as = hi;
        *(uint2*)(as + 2048) = lo;
    }

    // ldmatrix lane addressing (tiled128, x2 tile stride for k=16 chunks)
    const uint32_t lb = (uint32_t)((lane & 7) * 16);
    const uint32_t ab1 = (uint32_t)((lane >> 3) & 1);
    const uint32_t ab2 = (uint32_t)(lane >> 4);

    for (int kc = 0; kc < NCH; kc++) {
        asm volatile("cp.async.wait_group 2;");   // G_kc complete
        __syncthreads();
        stageG(kc + 3);

        // convert X(kc+1) -> A slot (kc+1)&1 (used next iteration)
        if (kc + 1 < NCH) {
            float4 v = *(const float4*)(smem + (uint32_t)((kc + 1) & 3) * 4096u + cxread);
            uint2 hi, lo;
            cvt_hilo(v.x, v.y, hi.x, lo.x);
            cvt_hilo(v.z, v.w, hi.y, lo.y);
            char* as = smem + AOFF + (uint32_t)((kc + 1) & 1) * 4096u + cwrit;
            *(uint2*)as = hi;
            *(uint2*)(as + 2048) = lo;
        }

        const uint32_t Abase = sb + AOFF + (uint32_t)(kc & 1) * 4096u;
        const uint32_t Bbase = sb + BOFF + (uint32_t)(kc & 3) * 8192u;

        uint32_t Ahi[2][4], Alo[2][4];
#pragma unroll
        for (int mt = 0; mt < 2; mt++) {
            uint32_t tix = ((uint32_t)(wm * 4 + mt * 2) + ab1) * 2 + ab2;
            uint32_t addr = Abase + tix * 128u + lb;
            ldsm4(Ahi[mt], addr);
            ldsm4(Alo[mt], addr + 2048u);
        }
        uint32_t Bhi[2][4], Blo[2][4];
#pragma unroll
        for (int ntp = 0; ntp < 2; ntp++) {
            uint32_t tix = ((uint32_t)(wn * 4 + ntp * 2) + ab2) * 2 + ab1;
            uint32_t addr = Bbase + tix * 128u + lb;
            ldsm4(Bhi[ntp], addr);
            ldsm4(Blo[ntp], addr + 4096u);
        }

        // term-major: 8 independent MMAs per term (reuse distance 8)
#pragma unroll
        for (int mt = 0; mt < 2; mt++)
#pragma unroll
            for (int ntp = 0; ntp < 2; ntp++)
#pragma unroll
                for (int sub = 0; sub < 2; sub++)
                    mma_bf16(acc[mt][ntp * 2 + sub], Ahi[mt],
                             Bhi[ntp][sub * 2], Bhi[ntp][sub * 2 + 1]);
#pragma unroll
        for (int mt = 0; mt < 2; mt++)
#pragma unroll
            for (int ntp = 0; ntp < 2; ntp++)
#pragma unroll
                for (int sub = 0; sub < 2; sub++)
                    mma_bf16(acc[mt][ntp * 2 + sub], Ahi[mt],
                             Blo[ntp][sub * 2], Blo[ntp][sub * 2 + 1]);
#pragma unroll
        for (int mt = 0; mt < 2; mt++)
#pragma unroll
            for (int ntp = 0; ntp < 2; ntp++)
#pragma unroll
                for (int sub = 0; sub < 2; sub++)
                    mma_bf16(acc[mt][ntp * 2 + sub], Alo[mt],
                             Bhi[ntp][sub * 2], Bhi[ntp][sub * 2 + 1]);
    }

    // Epilogue: per row, sum over this warp's 32 cols of V[n]*tanh(acc+l)
#pragma unroll
    for (int mt = 0; mt < 2; mt++) {
#pragma unroll
        for (int rh = 0; rh < 2; rh++) {
            int rowl = wm * 32 + mt * 16 + rh * 8 + (lane >> 2);
            int rowg = m * 64 + rowl;
            const float* lr = g_l + (rowg / SS) * HH + nh * 128;
            float s = 0.0f;
#pragma unroll
            for (int nt = 0; nt < 4; nt++) {
#pragma unroll
                for (int cl = 0; cl < 2; cl++) {
                    int col = wn * 32 + nt * 8 + (lane & 3) * 2 + cl;
                    float v = acc[mt][nt][rh * 2 + cl] + __ldg(lr + col);
                    s = fmaf(vsm[col], tanh_fma(v), s);
                }
            }
            s += __shfl_xor_sync(0xffffffffu, s, 1);
            s += __shfl_xor_sync(0xffffffffu, s, 2);
            if ((lane & 3) == 0) s_red[wn][rowl] = s;
        }
    }
    __syncthreads();
    if (tid < 64)
        g_sc[nh * MROWS + m * 64 + tid] =
            (s_red[0][tid] + s_red[1][tid]) + (s_red[2][tid] + s_red[3][tid]);
}

// ---------------------------------------------------------------------------
// softmax over S + pooled + final projection (R10-proven)
// ---------------------------------------------------------------------------
__global__ void __launch_bounds__(256) pool_kernel(const float* __restrict__ X,
                                                   const float* __restrict__ MW,
                                                   const float* __restrict__ Mb,
                                                   float* __restrict__ out) {
    __shared__ float sal[SS];
    __shared__ float red[8];
    __shared__ float4 red4[8];

    const int b = blockIdx.x;
    const int tid = threadIdx.x;
    const int lane = tid & 31;
    const int w = tid >> 5;

    float v;
    if (tid < SS) {
        int idx = b * SS + tid;
        v = g_sc[idx] + g_sc[MROWS + idx];
    } else {
        v = __int_as_float(0xff800000);
    }
    float mx = v;
#pragma unroll
    for (int o = 16; o; o >>= 1) mx = fmaxf(mx, __shfl_xor_sync(0xffffffffu, mx, o));
    if (lane == 0) red[w] = mx;
    __syncthreads();
    float bm = red[0];
#pragma unroll
    for (int i = 1; i < 8; i++) bm = fmaxf(bm, red[i]);

    float e = (tid < SS) ? __expf(v - bm) : 0.0f;
    float s = e;
#pragma unroll
    for (int o = 16; o; o >>= 1) s += __shfl_xor_sync(0xffffffffu, s, o);
    __syncthreads();
    if (lane == 0) red[w] = s;
    __syncthreads();
    float bs = 0.0f;
#pragma unroll
    for (int i = 0; i < 8; i++) bs += red[i];

    if (tid < SS) sal[tid] = e / bs;
    __syncthreads();

    const float* Xb = X + (size_t)b * SS * HH + tid;
    float acc = 0.0f;
#pragma unroll 8
    for (int sdx = 0; sdx < SS; sdx++)
        acc = fmaf(sal[sdx], Xb[(size_t)sdx * HH], acc);

    float4 p;
    p.x = acc * MW[0 * HH + tid];
    p.y = acc * MW[1 * HH + tid];
    p.z = acc * MW[2 * HH + tid];
    p.w = acc * MW[3 * HH + tid];
#pragma unroll
    for (int o = 16; o; o >>= 1) {
        p.x += __shfl_xor_sync(0xffffffffu, p.x, o);
        p.y += __shfl_xor_sync(0xffffffffu, p.y, o);
        p.z += __shfl_xor_sync(0xffffffffu, p.z, o);
        p.w += __shfl_xor_sync(0xffffffffu, p.w, o);
    }
    if (lane == 0) red4[w] = p;
    __syncthreads();
    if (tid == 0) {
        float4 t = red4[0];
#pragma unroll
        for (int i = 1; i < 8; i++) {
            t.x += red4[i].x; t.y += red4[i].y; t.z += red4[i].z; t.w += red4[i].w;
        }
        out[b * 4 + 0] = t.x + Mb[0];
        out[b * 4 + 1] = t.y + Mb[1];
        out[b * 4 + 2] = t.z + Mb[2];
        out[b * 4 + 3] = t.w + Mb[3];
    }
}

// ---------------------------------------------------------------------------
extern "C" void kernel_launch(void* const* d_in, const int* in_sizes, int n_in,
                              void* d_out, int out_size) {
    const float* X     = (const float*)d_in[0];
    const float* lastm = (const float*)d_in[1];
    const float* U     = (const float*)d_in[2];
    const float* W     = (const float*)d_in[3];
    const float* Vv    = (const float*)d_in[4];
    const float* MW    = (const float*)d_in[5];
    const float* Mb    = (const float*)d_in[6];
    float* out = (float*)d_out;

    char* uc;
    cudaGetSymbolAddress((void**)&uc, g_Uc);

    cudaFuncSetAttribute(gemm_kernel, cudaFuncAttributeMaxDynamicSharedMemorySize, GEMM_SMEM);

    conv_kernel<<<2 * NCH, 128>>>(U, uc);               // U -> tiled128 (k=16)
    l_kernel<<<BB, 256>>>(lastm, W);
    gemm_kernel<<<dim3(MT64, 2), 256, GEMM_SMEM>>>(X, Vv);
    pool_kernel<<<BB, 256>>>(X, MW, Mb, out);
}

// round 16
// speedup vs baseline: 1.2512x; 1.0099x over previous
#include <cuda_runtime.h>
#include <cuda_bf16.h>
#include <cstdint>

#define BB 512
#define SS 200
#define HH 256
#define MROWS (BB * SS)        // 102400 = 1600 * 64
#define MT64 1600
#define NCH 16                 // K chunks of 16
#define UCHUNK 8192            // U chunk: hi 4KB | lo 4KB (tiled128, 128 cols x 16 k)

// ---------------- scratch (no cudaMalloc allowed) ----------------
__device__ float g_l[BB * HH];
__device__ float g_sc[2 * MROWS];            // partial scores per n-half
__device__ __align__(128) char g_Uc[2 * NCH * UCHUNK];   // 256KB

// ---------------- helpers ----------------
__device__ __forceinline__ uint32_t smem_u32(const void* p) {
    uint32_t a;
    asm("{ .reg .u64 t; cvta.to.shared.u64 t, %1; cvt.u32.u64 %0, t; }" : "=r"(a) : "l"(p));
    return a;
}
__device__ __forceinline__ uint32_t pack_bf2(float x, float y) {
    uint32_t a = (uint32_t)__bfloat16_as_ushort(__float2bfloat16_rn(x));
    uint32_t b = (uint32_t)__bfloat16_as_ushort(__float2bfloat16_rn(y));
    return a | (b << 16);
}
__device__ __forceinline__ void cvt_hilo(float x, float y, uint32_t& hi, uint32_t& lo) {
    hi = pack_bf2(x, y);
    float h0 = __int_as_float(hi << 16);
    float h1 = __int_as_float(hi & 0xffff0000u);
    lo = pack_bf2(x - h0, y - h1);
}

// MUFU-free tanh (FMA/ALU pipes only); |err| <= ~3.4e-5
__device__ __forceinline__ float tanh_fma(float x) {
    float t = fminf(fabsf(x), 5.5f) * 2.8853900817779268f;  // 2*log2(e)*|x|
    int n = __float2int_rn(t);
    float f = t - (float)n;
    float p = 1.5403530393381608e-4f;
    p = fmaf(p, f, 1.3333558146428443e-3f);
    p = fmaf(p, f, 9.6181291076284772e-3f);
    p = fmaf(p, f, 5.5504108664821580e-2f);
    p = fmaf(p, f, 2.4022650695910071e-1f);
    p = fmaf(p, f, 6.9314718055994531e-1f);
    p = fmaf(p, f, 1.0f);
    float E = __int_as_float(__float_as_int(p) + (n << 23)); // e^{2|x|}
    float D = E + 1.0f;
    float r = __int_as_float(0x7EF311C3 - __float_as_int(D));
    r = r * fmaf(-D, r, 2.0f);
    r = r * fmaf(-D, r, 2.0f);
    r = r * fmaf(-D, r, 2.0f);
    float y = fmaf(-2.0f, r, 1.0f);
    return copysignf(y, x);
}

__device__ __forceinline__ void ldsm4(uint32_t* r, uint32_t addr) {
    asm volatile("ldmatrix.sync.aligned.m8n8.x4.shared.b16 {%0,%1,%2,%3}, [%4];"
                 : "=r"(r[0]), "=r"(r[1]), "=r"(r[2]), "=r"(r[3]) : "r"(addr));
}
__device__ __forceinline__ void mma_bf16(float* c, const uint32_t* a, uint32_t b0, uint32_t b1) {
    asm volatile(
        "mma.sync.aligned.m16n8k16.row.col.f32.bf16.bf16.f32 "
        "{%0,%1,%2,%3}, {%4,%5,%6,%7}, {%8,%9}, {%0,%1,%2,%3};"
        : "+f"(c[0]), "+f"(c[1]), "+f"(c[2]), "+f"(c[3])
        : "r"(a[0]), "r"(a[1]), "r"(a[2]), "r"(a[3]), "r"(b0), "r"(b1));
}
#define CPA16(dst, src) \
    asm volatile("cp.async.cg.shared.global [%0], [%1], 16;" :: "r"(dst), "l"(src))

// ---------------------------------------------------------------------------
// conv (U only): fp32 -> tiled128 bf16 hi/lo, chunks of k=16.
// ---------------------------------------------------------------------------
__global__ void __launch_bounds__(128) conv_kernel(const float* __restrict__ S,
                                                   char* __restrict__ D) {
    const int blk = blockIdx.x;
    const int kc = blk & 15;
    const int r = threadIdx.x;

    const float* src = S + (size_t)((blk >> 4) * 128 + r) * HH + kc * 16;
    char* dst = D + (size_t)blk * UCHUNK;
    const uint32_t rowbase = (uint32_t)((r >> 3) * 2 * 128 + (r & 7) * 16);

#pragma unroll
    for (int q = 0; q < 4; q++) {
        float4 v = *(const float4*)(src + q * 4);
        uint2 ph, pl;
        cvt_hilo(v.x, v.y, ph.x, pl.x);
        cvt_hilo(v.z, v.w, ph.y, pl.y);
        uint32_t off = rowbase + (uint32_t)((q >> 1) * 128 + (q & 1) * 8);
        *(uint2*)(dst + off) = ph;
        *(uint2*)(dst + 4096 + off) = pl;
    }
}

// ---------------------------------------------------------------------------
// l[b,k] = sum_h W[k,h] * last_memory[b,h]
// ---------------------------------------------------------------------------
__global__ void __launch_bounds__(256) l_kernel(const float* __restrict__ lastm,
                                                const float* __restrict__ W) {
    __shared__ float lm[HH];
    __shared__ float Wt[32][HH + 1];
    const int b = blockIdx.x;
    const int tid = threadIdx.x;

    lm[tid] = lastm[b * HH + tid];
    __syncthreads();

    float acc = 0.0f;
    for (int h0 = 0; h0 < HH; h0 += 32) {
#pragma unroll
        for (int q = 0; q < 8; q++) {
            int f = tid + 256 * q;
            int k = f >> 3;
            int hq = f & 7;
            float4 v = *(const float4*)(W + k * HH + h0 + hq * 4);
            Wt[hq * 4 + 0][k] = v.x;
            Wt[hq * 4 + 1][k] = v.y;
            Wt[hq * 4 + 2][k] = v.z;
            Wt[hq * 4 + 3][k] = v.w;
        }
        __syncthreads();
#pragma unroll
        for (int hh = 0; hh < 32; hh++)
            acc = fmaf(Wt[hh][tid], lm[h0 + hh], acc);
        __syncthreads();
    }
    g_l[b * HH + tid] = acc;
}

// ---------------------------------------------------------------------------
// GEMM (fused conv-X): CTA = 64 rows x 128 cols, 256 thr = 8 warps (2m x 4n),
// warp tile 32x32, 3 CTAs/SM. X fp32 ring x4 (80B-padded rows to cut the
// convert's LDS bank conflicts), converted to tiled128 A one chunk ahead,
// AFTER the MMA issue block. B ring x4, prefetch distance 3. 1 sync/chunk.
// smem: [X 4x5120 @0][A 2x4KB @20480][B 4x8KB @28672] = 60KB.
// ---------------------------------------------------------------------------
constexpr uint32_t XSLOT = 5120;       // 64 rows x 80B
constexpr uint32_t AOFF = 20480;
constexpr uint32_t BOFF = 28672;
constexpr uint32_t GEMM_SMEM = 61440;  // 60KB -> 3 CTAs/SM

__global__ void __launch_bounds__(256, 3) gemm_kernel(const float* __restrict__ X,
                                                      const float* __restrict__ Vv) {
    extern __shared__ __align__(1024) char smem[];
    __shared__ float vsm[128];
    __shared__ float s_red[4][64];

    const uint32_t sb = smem_u32(smem);
    const int tid = threadIdx.x;
    const int lane = tid & 31;
    const int wid = tid >> 5;
    const int wm = wid & 1;       // 2 m-warps x 32 rows
    const int wn = wid >> 1;      // 4 n-warps x 32 cols
    const int m = blockIdx.x;     // 64-row tile
    const int nh = blockIdx.y;

    if (tid < 128) vsm[tid] = Vv[nh * 128 + tid];

    float acc[2][4][4];
#pragma unroll
    for (int i = 0; i < 2; i++)
#pragma unroll
        for (int j = 0; j < 4; j++)
#pragma unroll
            for (int k = 0; k < 4; k++) acc[i][j][k] = 0.0f;

    // convert geometry: thread = (row = tid>>2, seg = tid&3 -> 4 floats)
    const int crow = tid >> 2;
    const int cseg = tid & 3;
    const uint32_t cxoff = (uint32_t)(crow * 80 + cseg * 16);      // padded row
    const uint32_t cwrit = (uint32_t)(((crow >> 3) * 2 + (cseg >> 1)) * 128
                                      + (crow & 7) * 16 + (cseg & 1) * 8);
    const char* xbase = (const char*)(X + (size_t)m * 64 * HH)
                      + (size_t)crow * (HH * 4) + cseg * 16;

    // group G_j = { B(j) -> Bslot j%4 ; X(j+1) -> Xslot (j+1)%4 }
    auto stageG = [&](int j) {
        if (j < NCH) {
            const char* us = g_Uc + ((size_t)nh * NCH + j) * UCHUNK;
            uint32_t o = (uint32_t)tid * 32u;
            uint32_t d = sb + BOFF + (uint32_t)(j & 3) * 8192u + o;
            CPA16(d, us + o); CPA16(d + 16u, us + o + 16);
            int jx = j + 1;
            if (jx < NCH)
                CPA16(sb + (uint32_t)(jx & 3) * XSLOT + cxoff, xbase + jx * 64);
        }
        asm volatile("cp.async.commit_group;");
    };

    // prologue: P = {X(0)}, then G_0, G_1, G_2
    CPA16(sb + cxoff, xbase);
    asm volatile("cp.async.commit_group;");
    stageG(0); stageG(1); stageG(2);

    asm volatile("cp.async.wait_group 3;");   // P done
    __syncthreads();
    {   // convert X(0) -> A slot 0
        float4 v = *(const float4*)(smem + cxoff);
        uint2 hi, lo;
        cvt_hilo(v.x, v.y, hi.x, lo.x);
        cvt_hilo(v.z, v.w, hi.y, lo.y);
        char* as = smem + AOFF + cwrit;
        *(uint2*)as = hi;
        *(uint2*)(as + 2048) = lo;
    }

    // ldmatrix lane addressing (tiled128)
    const uint32_t lb = (uint32_t)((lane & 7) * 16);
    const uint32_t ab1 = (uint32_t)((lane >> 3) & 1);
    const uint32_t ab2 = (uint32_t)(lane >> 4);

    for (int kc = 0; kc < NCH; kc++) {
        asm volatile("cp.async.wait_group 2;");   // G_kc complete
        __syncthreads();
        stageG(kc + 3);

        const uint32_t Abase = sb + AOFF + (uint32_t)(kc & 1) * 4096u;
        const uint32_t Bbase = sb + BOFF + (uint32_t)(kc & 3) * 8192u;

        uint32_t Ahi[2][4], Alo[2][4];
#pragma unroll
        for (int mt = 0; mt < 2; mt++) {
            uint32_t tix = ((uint32_t)(wm * 4 + mt * 2) + ab1) * 2 + ab2;
            uint32_t addr = Abase + tix * 128u + lb;
            ldsm4(Ahi[mt], addr);
            ldsm4(Alo[mt], addr + 2048u);
        }
        uint32_t Bhi[2][4], Blo[2][4];
#pragma unroll
        for (int ntp = 0; ntp < 2; ntp++) {
            uint32_t tix = ((uint32_t)(wn * 4 + ntp * 2) + ab2) * 2 + ab1;
            uint32_t addr = Bbase + tix * 128u + lb;
            ldsm4(Bhi[ntp], addr);
            ldsm4(Blo[ntp], addr + 4096u);
        }

        // term-major: 8 independent MMAs per term (reuse distance 8)
#pragma unroll
        for (int mt = 0; mt < 2; mt++)
#pragma unroll
            for (int ntp = 0; ntp < 2; ntp++)
#pragma unroll
                for (int sub = 0; sub < 2; sub++)
                    mma_bf16(acc[mt][ntp * 2 + sub], Ahi[mt],
                             Bhi[ntp][sub * 2], Bhi[ntp][sub * 2 + 1]);
#pragma unroll
        for (int mt = 0; mt < 2; mt++)
#pragma unroll
            for (int ntp = 0; ntp < 2; ntp++)
#pragma unroll
                for (int sub = 0; sub < 2; sub++)
                    mma_bf16(acc[mt][ntp * 2 + sub], Ahi[mt],
                             Blo[ntp][sub * 2], Blo[ntp][sub * 2 + 1]);
#pragma unroll
        for (int mt = 0; mt < 2; mt++)
#pragma unroll
            for (int ntp = 0; ntp < 2; ntp++)
#pragma unroll
                for (int sub = 0; sub < 2; sub++)
                    mma_bf16(acc[mt][ntp * 2 + sub], Alo[mt],
                             Bhi[ntp][sub * 2], Bhi[ntp][sub * 2 + 1]);

        // convert X(kc+1) -> A slot (kc+1)&1 (needed only after next sync;
        // placed after MMA issue so it fills the tensor-pipe tail)
        if (kc + 1 < NCH) {
            float4 v = *(const float4*)(smem + (uint32_t)((kc + 1) & 3) * XSLOT + cxoff);
            uint2 hi, lo;
            cvt_hilo(v.x, v.y, hi.x, lo.x);
            cvt_hilo(v.z, v.w, hi.y, lo.y);
            char* as = smem + AOFF + (uint32_t)((kc + 1) & 1) * 4096u + cwrit;
            *(uint2*)as = hi;
            *(uint2*)(as + 2048) = lo;
        }
    }

    // Epilogue: per row, sum over this warp's 32 cols of V[n]*tanh(acc+l)
#pragma unroll
    for (int mt = 0; mt < 2; mt++) {
#pragma unroll
        for (int rh = 0; rh < 2; rh++) {
            int rowl = wm * 32 + mt * 16 + rh * 8 + (lane >> 2);
            int rowg = m * 64 + rowl;
            const float* lr = g_l + (rowg / SS) * HH + nh * 128;
            float s = 0.0f;
#pragma unroll
            for (int nt = 0; nt < 4; nt++) {
#pragma unroll
                for (int cl = 0; cl < 2; cl++) {
                    int col = wn * 32 + nt * 8 + (lane & 3) * 2 + cl;
                    float v = acc[mt][nt][rh * 2 + cl] + __ldg(lr + col);
                    s = fmaf(vsm[col], tanh_fma(v), s);
                }
            }
            s += __shfl_xor_sync(0xffffffffu, s, 1);
            s += __shfl_xor_sync(0xffffffffu, s, 2);
            if ((lane & 3) == 0) s_red[wn][rowl] = s;
        }
    }
    __syncthreads();
    if (tid < 64)
        g_sc[nh * MROWS + m * 64 + tid] =
            (s_red[0][tid] + s_red[1][tid]) + (s_red[2][tid] + s_red[3][tid]);
}

// ---------------------------------------------------------------------------
// softmax over S + pooled (512 thr, S split in halves for 2x MLP) + projection
// ---------------------------------------------------------------------------
__global__ void __launch_bounds__(512) pool_kernel(const float* __restrict__ X,
                                                   const float* __restrict__ MW,
                                                   const float* __restrict__ Mb,
                                                   float* __restrict__ out) {
    __shared__ float sal[SS];
    __shared__ float red[16];
    __shared__ float4 red4[8];
    __shared__ float part[2][HH];

    const int b = blockIdx.x;
    const int tid = threadIdx.x;
    const int lane = tid & 31;
    const int w = tid >> 5;

    float v;
    if (tid < SS) {
        int idx = b * SS + tid;
        v = g_sc[idx] + g_sc[MROWS + idx];
    } else {
        v = __int_as_float(0xff800000);
    }
    float mx = v;
#pragma unroll
    for (int o = 16; o; o >>= 1) mx = fmaxf(mx, __shfl_xor_sync(0xffffffffu, mx, o));
    if (lane == 0) red[w] = mx;
    __syncthreads();
    float bm = red[0];
#pragma unroll
    for (int i = 1; i < 16; i++) bm = fmaxf(bm, red[i]);

    float e = (tid < SS) ? __expf(v - bm) : 0.0f;
    float s = e;
#pragma unroll
    for (int o = 16; o; o >>= 1) s += __shfl_xor_sync(0xffffffffu, s, o);
    __syncthreads();
    if (lane == 0) red[w] = s;
    __syncthreads();
    float bs = 0.0f;
#pragma unroll
    for (int i = 0; i < 16; i++) bs += red[i];

    if (tid < SS) sal[tid] = e / bs;
    __syncthreads();

    // pooling: thread = (half = tid>>8, h = tid&255), 100 rows per half
    {
        const int half = tid >> 8;
        const int h = tid & 255;
        const float* Xb = X + (size_t)b * SS * HH + h;
        const int s0 = half * 100;
        float acc = 0.0f;
#pragma unroll 10
        for (int sdx = s0; sdx < s0 + 100; sdx++)
            acc = fmaf(sal[sdx], Xb[(size_t)sdx * HH], acc);
        part[half][h] = acc;
    }
    __syncthreads();

    // projection: threads 0-255 (warps 0-7)
    if (tid < HH) {
        float acc = part[0][tid] + part[1][tid];
        float4 p;
        p.x = acc * MW[0 * HH + tid];
        p.y = acc * MW[1 * HH + tid];
        p.z = acc * MW[2 * HH + tid];
        p.w = acc * MW[3 * HH + tid];
#pragma unroll
        for (int o = 16; o; o >>= 1) {
            p.x += __shfl_xor_sync(0xffffffffu, p.x, o);
            p.y += __shfl_xor_sync(0xffffffffu, p.y, o);
            p.z += __shfl_xor_sync(0xffffffffu, p.z, o);
            p.w += __shfl_xor_sync(0xffffffffu, p.w, o);
        }
        if (lane == 0) red4[w] = p;
    }
    __syncthreads();
    if (tid == 0) {
        float4 t = red4[0];
#pragma unroll
        for (int i = 1; i < 8; i++) {
            t.x += red4[i].x; t.y += red4[i].y; t.z += red4[i].z; t.w += red4[i].w;
        }
        out[b * 4 + 0] = t.x + Mb[0];
        out[b * 4 + 1] = t.y + Mb[1];
        out[b * 4 + 2] = t.z + Mb[2];
        out[b * 4 + 3] = t.w + Mb[3];
    }
}

// ---------------------------------------------------------------------------
extern "C" void kernel_launch(void* const* d_in, const int* in_sizes, int n_in,
                              void* d_out, int out_size) {
    const float* X     = (const float*)d_in[0];
    const float* lastm = (const float*)d_in[1];
    const float* U     = (const float*)d_in[2];
    const float* W     = (const float*)d_in[3];
    const float* Vv    = (const float*)d_in[4];
    const float* MW    = (const float*)d_in[5];
    const float* Mb    = (const float*)d_in[6];
    float* out = (float*)d_out;

    char* uc;
    cudaGetSymbolAddress((void**)&uc, g_Uc);

    cudaFuncSetAttribute(gemm_kernel, cudaFuncAttributeMaxDynamicSharedMemorySize, GEMM_SMEM);

    conv_kernel<<<2 * NCH, 128>>>(U, uc);               // U -> tiled128 (k=16)
    l_kernel<<<BB, 256>>>(lastm, W);
    gemm_kernel<<<dim3(MT64, 2), 256, GEMM_SMEM>>>(X, Vv);
    pool_kernel<<<BB, 512>>>(X, MW, Mb, out);
}